// round 2
// baseline (speedup 1.0000x reference)
#include <cuda_runtime.h>

#define B_  4
#define L_  2048
#define D_  1024
#define H_  16
#define HD_ 64
#define M_  (B_ * L_)

// Scratch (device globals: allocation-free per harness rules)
__device__ float g_Q[(size_t)M_ * D_];
__device__ float g_K[(size_t)M_ * D_];
__device__ float g_V[(size_t)M_ * D_];
__device__ float g_C[(size_t)M_ * D_];

// ---------------------------------------------------------------------------
// C[m][n] = sum_k A[m][k] * B[n][k]   (both operands K-contiguous, "NT" GEMM)
// 128x128 block tile, 16-wide K tile, 8x8 per thread, 256 threads.
// ---------------------------------------------------------------------------
__global__ __launch_bounds__(256, 2) void sgemm_nt(
    const float* __restrict__ A, const float* __restrict__ Bw,
    float* __restrict__ C, int M, int N, int K)
{
    __shared__ float As[16][132];
    __shared__ float Bs[16][132];

    const int tid = threadIdx.x;
    const int tx  = tid & 15;   // n-direction
    const int ty  = tid >> 4;   // m-direction
    const int m0  = blockIdx.y << 7;
    const int n0  = blockIdx.x << 7;

    float acc[8][8];
#pragma unroll
    for (int i = 0; i < 8; i++)
#pragma unroll
        for (int j = 0; j < 8; j++) acc[i][j] = 0.f;

    const int lrow = tid >> 2;        // 0..63
    const int lc4  = (tid & 3) << 2;  // 0,4,8,12

    const float* Ap = A  + (size_t)(m0 + lrow) * K + lc4;
    const float* Bp = Bw + (size_t)(n0 + lrow) * K + lc4;

    for (int k0 = 0; k0 < K; k0 += 16) {
#pragma unroll
        for (int p = 0; p < 2; p++) {
            float4 va = *reinterpret_cast<const float4*>(Ap + (size_t)(p * 64) * K + k0);
            As[lc4 + 0][lrow + p * 64] = va.x;
            As[lc4 + 1][lrow + p * 64] = va.y;
            As[lc4 + 2][lrow + p * 64] = va.z;
            As[lc4 + 3][lrow + p * 64] = va.w;
            float4 vb = *reinterpret_cast<const float4*>(Bp + (size_t)(p * 64) * K + k0);
            Bs[lc4 + 0][lrow + p * 64] = vb.x;
            Bs[lc4 + 1][lrow + p * 64] = vb.y;
            Bs[lc4 + 2][lrow + p * 64] = vb.z;
            Bs[lc4 + 3][lrow + p * 64] = vb.w;
        }
        __syncthreads();

#pragma unroll
        for (int kk = 0; kk < 16; kk++) {
            float a[8], b[8];
            float4 t;
            t = *reinterpret_cast<const float4*>(&As[kk][ty * 8]);
            a[0] = t.x; a[1] = t.y; a[2] = t.z; a[3] = t.w;
            t = *reinterpret_cast<const float4*>(&As[kk][ty * 8 + 4]);
            a[4] = t.x; a[5] = t.y; a[6] = t.z; a[7] = t.w;
            t = *reinterpret_cast<const float4*>(&Bs[kk][tx * 8]);
            b[0] = t.x; b[1] = t.y; b[2] = t.z; b[3] = t.w;
            t = *reinterpret_cast<const float4*>(&Bs[kk][tx * 8 + 4]);
            b[4] = t.x; b[5] = t.y; b[6] = t.z; b[7] = t.w;
#pragma unroll
            for (int i = 0; i < 8; i++)
#pragma unroll
                for (int j = 0; j < 8; j++) acc[i][j] += a[i] * b[j];
        }
        __syncthreads();
    }

#pragma unroll
    for (int i = 0; i < 8; i++) {
        float* Cp = C + (size_t)(m0 + ty * 8 + i) * N + n0 + tx * 8;
        *reinterpret_cast<float4*>(Cp)     = make_float4(acc[i][0], acc[i][1], acc[i][2], acc[i][3]);
        *reinterpret_cast<float4*>(Cp + 4) = make_float4(acc[i][4], acc[i][5], acc[i][6], acc[i][7]);
    }
}

// ---------------------------------------------------------------------------
// Flash attention: one block = one (b, h, 64-query tile). Online softmax.
// K-tile smem buffer is reused to hold P (exp(S - m)) for the PV GEMM.
// ---------------------------------------------------------------------------
#define SQ 65  // padded row stride for Qs / KPs (bank-conflict avoidance)

__global__ __launch_bounds__(256, 2) void flash64(
    const float* __restrict__ Q, const float* __restrict__ K,
    const float* __restrict__ V, float* __restrict__ O)
{
    extern __shared__ float sm[];
    float* Qs  = sm;                 // 64 x 65
    float* KPs = sm + 64 * SQ;       // 64 x 65 (K tile, then P tile)
    float* Vs  = sm + 2 * 64 * SQ;   // 64 x 64

    const int tid = threadIdx.x;
    const int tx  = tid & 15;   // k-col group for S; d-col group for O
    const int ty  = tid >> 4;   // q-row group
    const int b   = blockIdx.z;
    const int h   = blockIdx.y;
    const int q0  = blockIdx.x << 6;

    const size_t base = ((size_t)b * L_) * D_ + (size_t)h * HD_;
    const float* Qb = Q + base + (size_t)q0 * D_;
    const float* Kb = K + base;
    const float* Vb = V + base;

    // Load Q tile (64x64), float4 from GMEM, scalar scatter into padded smem.
#pragma unroll
    for (int p = 0; p < 4; p++) {
        int idx = tid + (p << 8);
        int row = idx >> 4;
        int c4  = (idx & 15) << 2;
        float4 vq = *reinterpret_cast<const float4*>(Qb + (size_t)row * D_ + c4);
        Qs[row * SQ + c4 + 0] = vq.x;
        Qs[row * SQ + c4 + 1] = vq.y;
        Qs[row * SQ + c4 + 2] = vq.z;
        Qs[row * SQ + c4 + 3] = vq.w;
    }

    float m_i[4], l_i[4], acc[4][4];
#pragma unroll
    for (int i = 0; i < 4; i++) {
        m_i[i] = -1e30f;
        l_i[i] = 0.f;
#pragma unroll
        for (int j = 0; j < 4; j++) acc[i][j] = 0.f;
    }

    for (int kt = 0; kt < L_; kt += 64) {
        __syncthreads();  // previous iteration done with KPs/Vs (also covers Q load)
#pragma unroll
        for (int p = 0; p < 4; p++) {
            int idx = tid + (p << 8);
            int row = idx >> 4;
            int c4  = (idx & 15) << 2;
            float4 kv = *reinterpret_cast<const float4*>(Kb + (size_t)(kt + row) * D_ + c4);
            KPs[row * SQ + c4 + 0] = kv.x;
            KPs[row * SQ + c4 + 1] = kv.y;
            KPs[row * SQ + c4 + 2] = kv.z;
            KPs[row * SQ + c4 + 3] = kv.w;
            float4 vv = *reinterpret_cast<const float4*>(Vb + (size_t)(kt + row) * D_ + c4);
            Vs[row * 64 + c4 + 0] = vv.x;
            Vs[row * 64 + c4 + 1] = vv.y;
            Vs[row * 64 + c4 + 2] = vv.z;
            Vs[row * 64 + c4 + 3] = vv.w;
        }
        __syncthreads();

        // S = Q K^T  (4x4 per thread)
        float s[4][4];
#pragma unroll
        for (int i = 0; i < 4; i++)
#pragma unroll
            for (int j = 0; j < 4; j++) s[i][j] = 0.f;

#pragma unroll 8
        for (int d = 0; d < 64; d++) {
            float qv[4], kv[4];
#pragma unroll
            for (int i = 0; i < 4; i++) qv[i] = Qs[(ty * 4 + i) * SQ + d];
#pragma unroll
            for (int j = 0; j < 4; j++) kv[j] = KPs[(tx * 4 + j) * SQ + d];
#pragma unroll
            for (int i = 0; i < 4; i++)
#pragma unroll
                for (int j = 0; j < 4; j++) s[i][j] += qv[i] * kv[j];
        }

        // Online softmax update (rows distributed over tx: 16 lanes per row group)
#pragma unroll
        for (int i = 0; i < 4; i++) {
            float mt = -1e30f;
#pragma unroll
            for (int j = 0; j < 4; j++) {
                s[i][j] *= 0.125f;  // 1/sqrt(64)
                mt = fmaxf(mt, s[i][j]);
            }
#pragma unroll
            for (int ofs = 8; ofs > 0; ofs >>= 1)
                mt = fmaxf(mt, __shfl_xor_sync(0xffffffffu, mt, ofs));
            float m_new = fmaxf(m_i[i], mt);
            float alpha = __expf(m_i[i] - m_new);
            float r = 0.f;
#pragma unroll
            for (int j = 0; j < 4; j++) {
                s[i][j] = __expf(s[i][j] - m_new);
                r += s[i][j];
            }
#pragma unroll
            for (int ofs = 8; ofs > 0; ofs >>= 1)
                r += __shfl_xor_sync(0xffffffffu, r, ofs);
            l_i[i] = l_i[i] * alpha + r;
            m_i[i] = m_new;
#pragma unroll
            for (int j = 0; j < 4; j++) acc[i][j] *= alpha;
        }

        __syncthreads();  // everyone done reading K tile
#pragma unroll
        for (int i = 0; i < 4; i++)
#pragma unroll
            for (int j = 0; j < 4; j++)
                KPs[(ty * 4 + i) * SQ + tx * 4 + j] = s[i][j];
        __syncthreads();

        // acc += P @ V
#pragma unroll 8
        for (int k = 0; k < 64; k++) {
            float pv[4], vv[4];
#pragma unroll
            for (int i = 0; i < 4; i++) pv[i] = KPs[(ty * 4 + i) * SQ + k];
#pragma unroll
            for (int j = 0; j < 4; j++) vv[j] = Vs[k * 64 + tx * 4 + j];
#pragma unroll
            for (int i = 0; i < 4; i++)
#pragma unroll
                for (int j = 0; j < 4; j++) acc[i][j] += pv[i] * vv[j];
        }
    }

    // O = acc / l, written in the [b, l, h*HD + d] layout
    float* Ob = O + base + (size_t)q0 * D_;
#pragma unroll
    for (int i = 0; i < 4; i++) {
        float inv = 1.f / l_i[i];
        *reinterpret_cast<float4*>(Ob + (size_t)(ty * 4 + i) * D_ + tx * 4) =
            make_float4(acc[i][0] * inv, acc[i][1] * inv, acc[i][2] * inv, acc[i][3] * inv);
    }
}

// ---------------------------------------------------------------------------
extern "C" void kernel_launch(void* const* d_in, const int* in_sizes, int n_in,
                              void* d_out, int out_size)
{
    const float* q  = (const float*)d_in[0];
    const float* k  = (const float*)d_in[1];
    const float* v  = (const float*)d_in[2];
    const float* Wq = (const float*)d_in[3];
    const float* Wk = (const float*)d_in[4];
    const float* Wv = (const float*)d_in[5];
    const float* Wo = (const float*)d_in[6];
    float* out = (float*)d_out;

    float *gQ, *gK, *gV, *gC;
    cudaGetSymbolAddress((void**)&gQ, g_Q);
    cudaGetSymbolAddress((void**)&gK, g_K);
    cudaGetSymbolAddress((void**)&gV, g_V);
    cudaGetSymbolAddress((void**)&gC, g_C);

    const int smem = (2 * 64 * SQ + 64 * 64) * (int)sizeof(float);  // 49,664 B
    cudaFuncSetAttribute((const void*)flash64,
                         cudaFuncAttributeMaxDynamicSharedMemorySize, smem);

    dim3 gemm_grid(D_ / 128, M_ / 128);   // (8, 64)
    sgemm_nt<<<gemm_grid, 256>>>(q, Wq, gQ, M_, D_, D_);
    sgemm_nt<<<gemm_grid, 256>>>(k, Wk, gK, M_, D_, D_);
    sgemm_nt<<<gemm_grid, 256>>>(v, Wv, gV, M_, D_, D_);

    dim3 attn_grid(L_ / 64, H_, B_);      // (32, 16, 4)
    flash64<<<attn_grid, 256, smem>>>(gQ, gK, gV, gC);

    sgemm_nt<<<gemm_grid, 256>>>(gC, Wo, out, M_, D_, D_);
}

// round 5
// speedup vs baseline: 1.2211x; 1.2211x over previous
#include <cuda_runtime.h>
#include <cstdint>

#define B_  4
#define L_  2048
#define D_  1024
#define H_  16
#define HD_ 64
#define M_  (B_ * L_)

// Scratch (device globals: allocation-free per harness rules)
__device__ float g_Q[(size_t)M_ * D_];
__device__ float g_K[(size_t)M_ * D_];
__device__ float g_V[(size_t)M_ * D_];
__device__ float g_C[(size_t)M_ * D_];

// ============================================================================
// tf32 mma.sync GEMM:  C[m][n] = sum_k A[m][k] * W[n][k]
// M=8192, N=1024, K=1024.  128x128 CTA tile, BK=32, 256 threads (8 warps).
// Warp grid 4(m) x 2(n): warp tile 32x64 = 2 m-atoms x 8 n-atoms of m16n8k8.
// ============================================================================
#define GK    1024
#define BK    32
#define NCH   (GK / BK)       // 32 chunks
#define LDSW  36              // padded row stride (floats): conflict-free frags
#define STG_A (128 * LDSW)    // floats per A stage
// smem: As0 | As1 | Bs0 | Bs1
#define SM_FLOATS (4 * STG_A) // 18432 floats = 73728 bytes

__device__ __forceinline__ uint32_t f2tf32(float f) {
    uint32_t u;
    asm("cvt.rna.tf32.f32 %0, %1;" : "=r"(u) : "f"(f));
    return u;
}

__device__ __forceinline__ void mma_tf32(float* c, const uint32_t* a, const uint32_t* b) {
    asm volatile(
        "mma.sync.aligned.m16n8k8.row.col.f32.tf32.tf32.f32 "
        "{%0,%1,%2,%3}, {%4,%5,%6,%7}, {%8,%9}, {%0,%1,%2,%3};"
        : "+f"(c[0]), "+f"(c[1]), "+f"(c[2]), "+f"(c[3])
        : "r"(a[0]), "r"(a[1]), "r"(a[2]), "r"(a[3]), "r"(b[0]), "r"(b[1]));
}

__global__ __launch_bounds__(256, 1)
void gemm_mma(const float* __restrict__ A, const float* __restrict__ Bw,
              float* __restrict__ C)
{
    extern __shared__ float sm[];
    float* As[2] = { sm,             sm + STG_A };
    float* Bs[2] = { sm + 2 * STG_A, sm + 3 * STG_A };

    const int tid  = threadIdx.x;
    const int lane = tid & 31;
    const int warp = tid >> 5;
    const int wm   = warp >> 1;        // 0..3
    const int wn   = warp & 1;         // 0..1
    const int gid  = lane >> 2;        // 0..7
    const int tig  = lane & 3;         // 0..3
    const int m0   = blockIdx.y << 7;
    const int n0   = blockIdx.x << 7;

    const float* Ab = A  + (size_t)m0 * GK;
    const float* Bb = Bw + (size_t)n0 * GK;

    // per-thread GMEM->SMEM mapping: 4 float4 per operand per chunk
    const int grow = tid >> 3;          // 0..31 (row group base, +32 per p)
    const int gc4  = (tid & 7) << 2;    // 0,4,...,28

    float acc[2][8][4];
#pragma unroll
    for (int i = 0; i < 2; i++)
#pragma unroll
        for (int j = 0; j < 8; j++)
#pragma unroll
            for (int t = 0; t < 4; t++) acc[i][j][t] = 0.f;

    // prologue: chunk 0 -> stage 0
    {
        float* sA = As[0];
        float* sB = Bs[0];
#pragma unroll
        for (int p = 0; p < 4; ++p) {
            int row = grow + (p << 5);
            float4 va = *reinterpret_cast<const float4*>(Ab + (size_t)row * GK + gc4);
            float4 vb = *reinterpret_cast<const float4*>(Bb + (size_t)row * GK + gc4);
            uint32_t* da = reinterpret_cast<uint32_t*>(sA + row * LDSW + gc4);
            uint32_t* db = reinterpret_cast<uint32_t*>(sB + row * LDSW + gc4);
            da[0] = f2tf32(va.x); da[1] = f2tf32(va.y); da[2] = f2tf32(va.z); da[3] = f2tf32(va.w);
            db[0] = f2tf32(vb.x); db[1] = f2tf32(vb.y); db[2] = f2tf32(vb.z); db[3] = f2tf32(vb.w);
        }
    }
    __syncthreads();

    for (int c = 0; c < NCH; ++c) {
        const int buf = c & 1;

        // prefetch next chunk into registers (overlaps with mma below)
        float4 pa[4], pb[4];
        const bool more = (c + 1 < NCH);
        if (more) {
            const int k0 = (c + 1) * BK;
#pragma unroll
            for (int p = 0; p < 4; ++p) {
                int row = grow + (p << 5);
                pa[p] = *reinterpret_cast<const float4*>(Ab + (size_t)row * GK + k0 + gc4);
                pb[p] = *reinterpret_cast<const float4*>(Bb + (size_t)row * GK + k0 + gc4);
            }
        }

        // compute on current buffer
        const float* sA = As[buf];
        const float* sB = Bs[buf];
#pragma unroll
        for (int ks = 0; ks < 4; ++ks) {
            const int k = ks << 3;
            uint32_t af[2][4], bf[8][2];
#pragma unroll
            for (int ma = 0; ma < 2; ++ma) {
                const int mb = wm * 32 + ma * 16;
                const uint32_t* base = reinterpret_cast<const uint32_t*>(sA);
                af[ma][0] = base[(mb + gid) * LDSW + k + tig];
                af[ma][1] = base[(mb + gid + 8) * LDSW + k + tig];
                af[ma][2] = base[(mb + gid) * LDSW + k + tig + 4];
                af[ma][3] = base[(mb + gid + 8) * LDSW + k + tig + 4];
            }
#pragma unroll
            for (int na = 0; na < 8; ++na) {
                const int nb = wn * 64 + na * 8 + gid;
                const uint32_t* base = reinterpret_cast<const uint32_t*>(sB);
                bf[na][0] = base[nb * LDSW + k + tig];
                bf[na][1] = base[nb * LDSW + k + tig + 4];
            }
#pragma unroll
            for (int ma = 0; ma < 2; ++ma)
#pragma unroll
                for (int na = 0; na < 8; ++na)
                    mma_tf32(acc[ma][na], af[ma], bf[na]);
        }

        if (more) {
            __syncthreads();   // everyone done reading buf^1 from chunk c-1
            float* dAs = As[buf ^ 1];
            float* dBs = Bs[buf ^ 1];
#pragma unroll
            for (int p = 0; p < 4; ++p) {
                int row = grow + (p << 5);
                uint32_t* da = reinterpret_cast<uint32_t*>(dAs + row * LDSW + gc4);
                uint32_t* db = reinterpret_cast<uint32_t*>(dBs + row * LDSW + gc4);
                da[0] = f2tf32(pa[p].x); da[1] = f2tf32(pa[p].y);
                da[2] = f2tf32(pa[p].z); da[3] = f2tf32(pa[p].w);
                db[0] = f2tf32(pb[p].x); db[1] = f2tf32(pb[p].y);
                db[2] = f2tf32(pb[p].z); db[3] = f2tf32(pb[p].w);
            }
            __syncthreads();
        }
    }

    // epilogue: float2 stores (c0,c1 are adjacent columns)
#pragma unroll
    for (int ma = 0; ma < 2; ++ma) {
        const int row = m0 + wm * 32 + ma * 16 + gid;
#pragma unroll
        for (int na = 0; na < 8; ++na) {
            const int col = n0 + wn * 64 + na * 8 + tig * 2;
            *reinterpret_cast<float2*>(C + (size_t)row * D_ + col) =
                make_float2(acc[ma][na][0], acc[ma][na][1]);
            *reinterpret_cast<float2*>(C + (size_t)(row + 8) * D_ + col) =
                make_float2(acc[ma][na][2], acc[ma][na][3]);
        }
    }
}

// ============================================================================
// Flash attention (unchanged, validated R2): fp32 SIMT, online softmax.
// ============================================================================
#define SQ 65

__global__ __launch_bounds__(256, 2) void flash64(
    const float* __restrict__ Q, const float* __restrict__ K,
    const float* __restrict__ V, float* __restrict__ O)
{
    extern __shared__ float smf[];
    float* Qs  = smf;
    float* KPs = smf + 64 * SQ;
    float* Vs  = smf + 2 * 64 * SQ;

    const int tid = threadIdx.x;
    const int tx  = tid & 15;
    const int ty  = tid >> 4;
    const int b   = blockIdx.z;
    const int h   = blockIdx.y;
    const int q0  = blockIdx.x << 6;

    const size_t base = ((size_t)b * L_) * D_ + (size_t)h * HD_;
    const float* Qb = Q + base + (size_t)q0 * D_;
    const float* Kb = K + base;
    const float* Vb = V + base;

#pragma unroll
    for (int p = 0; p < 4; p++) {
        int idx = tid + (p << 8);
        int row = idx >> 4;
        int c4  = (idx & 15) << 2;
        float4 vq = *reinterpret_cast<const float4*>(Qb + (size_t)row * D_ + c4);
        Qs[row * SQ + c4 + 0] = vq.x;
        Qs[row * SQ + c4 + 1] = vq.y;
        Qs[row * SQ + c4 + 2] = vq.z;
        Qs[row * SQ + c4 + 3] = vq.w;
    }

    float m_i[4], l_i[4], acc[4][4];
#pragma unroll
    for (int i = 0; i < 4; i++) {
        m_i[i] = -1e30f; l_i[i] = 0.f;
#pragma unroll
        for (int j = 0; j < 4; j++) acc[i][j] = 0.f;
    }

    for (int kt = 0; kt < L_; kt += 64) {
        __syncthreads();
#pragma unroll
        for (int p = 0; p < 4; p++) {
            int idx = tid + (p << 8);
            int row = idx >> 4;
            int c4  = (idx & 15) << 2;
            float4 kv = *reinterpret_cast<const float4*>(Kb + (size_t)(kt + row) * D_ + c4);
            KPs[row * SQ + c4 + 0] = kv.x;
            KPs[row * SQ + c4 + 1] = kv.y;
            KPs[row * SQ + c4 + 2] = kv.z;
            KPs[row * SQ + c4 + 3] = kv.w;
            float4 vv = *reinterpret_cast<const float4*>(Vb + (size_t)(kt + row) * D_ + c4);
            Vs[row * 64 + c4 + 0] = vv.x;
            Vs[row * 64 + c4 + 1] = vv.y;
            Vs[row * 64 + c4 + 2] = vv.z;
            Vs[row * 64 + c4 + 3] = vv.w;
        }
        __syncthreads();

        float s[4][4];
#pragma unroll
        for (int i = 0; i < 4; i++)
#pragma unroll
            for (int j = 0; j < 4; j++) s[i][j] = 0.f;

#pragma unroll 8
        for (int d = 0; d < 64; d++) {
            float qv[4], kv[4];
#pragma unroll
            for (int i = 0; i < 4; i++) qv[i] = Qs[(ty * 4 + i) * SQ + d];
#pragma unroll
            for (int j = 0; j < 4; j++) kv[j] = KPs[(tx * 4 + j) * SQ + d];
#pragma unroll
            for (int i = 0; i < 4; i++)
#pragma unroll
                for (int j = 0; j < 4; j++) s[i][j] += qv[i] * kv[j];
        }

#pragma unroll
        for (int i = 0; i < 4; i++) {
            float mt = -1e30f;
#pragma unroll
            for (int j = 0; j < 4; j++) {
                s[i][j] *= 0.125f;
                mt = fmaxf(mt, s[i][j]);
            }
#pragma unroll
            for (int ofs = 8; ofs > 0; ofs >>= 1)
                mt = fmaxf(mt, __shfl_xor_sync(0xffffffffu, mt, ofs));
            float m_new = fmaxf(m_i[i], mt);
            float alpha = __expf(m_i[i] - m_new);
            float r = 0.f;
#pragma unroll
            for (int j = 0; j < 4; j++) {
                s[i][j] = __expf(s[i][j] - m_new);
                r += s[i][j];
            }
#pragma unroll
            for (int ofs = 8; ofs > 0; ofs >>= 1)
                r += __shfl_xor_sync(0xffffffffu, r, ofs);
            l_i[i] = l_i[i] * alpha + r;
            m_i[i] = m_new;
#pragma unroll
            for (int j = 0; j < 4; j++) acc[i][j] *= alpha;
        }

        __syncthreads();
#pragma unroll
        for (int i = 0; i < 4; i++)
#pragma unroll
            for (int j = 0; j < 4; j++)
                KPs[(ty * 4 + i) * SQ + tx * 4 + j] = s[i][j];
        __syncthreads();

#pragma unroll 8
        for (int k = 0; k < 64; k++) {
            float pv[4], vv[4];
#pragma unroll
            for (int i = 0; i < 4; i++) pv[i] = KPs[(ty * 4 + i) * SQ + k];
#pragma unroll
            for (int j = 0; j < 4; j++) vv[j] = Vs[k * 64 + tx * 4 + j];
#pragma unroll
            for (int i = 0; i < 4; i++)
#pragma unroll
                for (int j = 0; j < 4; j++) acc[i][j] += pv[i] * vv[j];
        }
    }

    float* Ob = O + base + (size_t)q0 * D_;
#pragma unroll
    for (int i = 0; i < 4; i++) {
        float inv = 1.f / l_i[i];
        *reinterpret_cast<float4*>(Ob + (size_t)(ty * 4 + i) * D_ + tx * 4) =
            make_float4(acc[i][0] * inv, acc[i][1] * inv, acc[i][2] * inv, acc[i][3] * inv);
    }
}

// ---------------------------------------------------------------------------
extern "C" void kernel_launch(void* const* d_in, const int* in_sizes, int n_in,
                              void* d_out, int out_size)
{
    const float* q  = (const float*)d_in[0];
    const float* k  = (const float*)d_in[1];
    const float* v  = (const float*)d_in[2];
    const float* Wq = (const float*)d_in[3];
    const float* Wk = (const float*)d_in[4];
    const float* Wv = (const float*)d_in[5];
    const float* Wo = (const float*)d_in[6];
    float* out = (float*)d_out;

    float *gQ, *gK, *gV, *gC;
    cudaGetSymbolAddress((void**)&gQ, g_Q);
    cudaGetSymbolAddress((void**)&gK, g_K);
    cudaGetSymbolAddress((void**)&gV, g_V);
    cudaGetSymbolAddress((void**)&gC, g_C);

    const int gsmem = SM_FLOATS * (int)sizeof(float);   // 73,728 B
    cudaFuncSetAttribute((const void*)gemm_mma,
                         cudaFuncAttributeMaxDynamicSharedMemorySize, gsmem);
    const int fsmem = (2 * 64 * SQ + 64 * 64) * (int)sizeof(float);
    cudaFuncSetAttribute((const void*)flash64,
                         cudaFuncAttributeMaxDynamicSharedMemorySize, fsmem);

    dim3 gemm_grid(D_ / 128, M_ / 128);   // (8, 64)
    gemm_mma<<<gemm_grid, 256, gsmem>>>(q, Wq, gQ);
    gemm_mma<<<gemm_grid, 256, gsmem>>>(k, Wk, gK);
    gemm_mma<<<gemm_grid, 256, gsmem>>>(v, Wv, gV);

    dim3 attn_grid(L_ / 64, H_, B_);      // (32, 16, 4)
    flash64<<<attn_grid, 256, fsmem>>>(gQ, gK, gV, gC);

    gemm_mma<<<gemm_grid, 256, gsmem>>>(gC, Wo, out);
}